// round 1
// baseline (speedup 1.0000x reference)
#include <cuda_runtime.h>
#include <math.h>

#define NN 100000
#define EE 1600000
#define DMAX 220
#define EPSV 1e-5f

// ---------------- device scratch (no allocations allowed) ----------------
__device__ float g_bufA[(size_t)NN * DMAX];   // GEMM output h
__device__ float g_bufB[(size_t)NN * DMAX];   // agg output / next layer input
__device__ int   g_deg[NN];
__device__ float g_dis[NN];
__device__ int   g_cnt[NN];
__device__ int   g_rowptr[NN + 1];
__device__ int   g_cursor[NN];
__device__ int   g_blocksum[256];
__device__ int   g_blockoff[256];
__device__ int   g_src[EE];
__device__ float g_w[EE];
__device__ float g_sums[256];
__device__ float g_sumsq[256];
__device__ float g_scale[256];
__device__ float g_shift[256];

// ---------------- preprocessing ----------------
__global__ void k_init() {
    int i = blockIdx.x * blockDim.x + threadIdx.x;
    if (i < NN) g_deg[i] = 1;   // self loop
}

__global__ void k_hist(const int* __restrict__ dst) {
    int e = blockIdx.x * blockDim.x + threadIdx.x;
    if (e < EE) atomicAdd(&g_deg[dst[e]], 1);
}

__global__ void k_dis() {
    int i = blockIdx.x * blockDim.x + threadIdx.x;
    if (i < NN) {
        int dg = g_deg[i];
        g_dis[i] = rsqrtf((float)dg);
        g_cnt[i] = dg - 1;
    }
}

__global__ void k_scan1() {
    __shared__ int sh[512];
    int i = blockIdx.x * 512 + threadIdx.x;
    int v = (i < NN) ? g_cnt[i] : 0;
    sh[threadIdx.x] = v;
    __syncthreads();
    #pragma unroll
    for (int off = 1; off < 512; off <<= 1) {
        int t = (threadIdx.x >= off) ? sh[threadIdx.x - off] : 0;
        __syncthreads();
        sh[threadIdx.x] += t;
        __syncthreads();
    }
    if (i < NN) g_rowptr[i] = sh[threadIdx.x] - v;          // exclusive
    if (threadIdx.x == 511) g_blocksum[blockIdx.x] = sh[511];
}

__global__ void k_scan2(int nb) {
    __shared__ int sh[256];
    int v = (threadIdx.x < nb) ? g_blocksum[threadIdx.x] : 0;
    sh[threadIdx.x] = v;
    __syncthreads();
    #pragma unroll
    for (int off = 1; off < 256; off <<= 1) {
        int t = (threadIdx.x >= off) ? sh[threadIdx.x - off] : 0;
        __syncthreads();
        sh[threadIdx.x] += t;
        __syncthreads();
    }
    if (threadIdx.x < nb) g_blockoff[threadIdx.x] = sh[threadIdx.x] - v;
}

__global__ void k_scan3() {
    int i = blockIdx.x * 512 + threadIdx.x;
    if (i < NN) {
        int r = g_rowptr[i] + g_blockoff[blockIdx.x];
        g_rowptr[i] = r;
        g_cursor[i] = r;
    }
    if (i == 0 && blockIdx.x == 0) g_rowptr[NN] = EE;
}

__global__ void k_fill(const int* __restrict__ ei) {
    int e = blockIdx.x * blockDim.x + threadIdx.x;
    if (e < EE) {
        int s  = ei[e];
        int dv = ei[EE + e];
        float w = g_dis[s] * g_dis[dv];
        int p = atomicAdd(&g_cursor[dv], 1);
        g_src[p] = s;
        g_w[p]   = w;
    }
}

// ---------------- SGEMM: C[M,N] = A[M,K] @ B[K,N], C -> g_bufA ----------------
__global__ void __launch_bounds__(256) k_sgemm(const float* __restrict__ X, int useX,
                                               const float* __restrict__ B,
                                               int M_, int K_, int N_) {
    const float* Ap = useX ? X : g_bufB;
    __shared__ float As[16][128];
    __shared__ float Bs[16][128];
    int tid = threadIdx.x;
    int bm = blockIdx.x * 128;
    int bn = blockIdx.y * 128;
    int tx = tid & 15, ty = tid >> 4;
    int row0 = ty * 8, col0 = tx * 8;
    float acc[8][8];
    #pragma unroll
    for (int i = 0; i < 8; i++)
        #pragma unroll
        for (int j = 0; j < 8; j++) acc[i][j] = 0.f;

    for (int k0 = 0; k0 < K_; k0 += 16) {
        #pragma unroll
        for (int i = 0; i < 8; i++) {
            int e = tid + i * 256;
            int r = e >> 4, c = e & 15;
            int gr = bm + r, gc = k0 + c;
            As[c][r] = (gr < M_ && gc < K_) ? Ap[(size_t)gr * K_ + gc] : 0.f;
        }
        #pragma unroll
        for (int i = 0; i < 8; i++) {
            int e = tid + i * 256;
            int r = e >> 7, c = e & 127;
            int gr = k0 + r, gc = bn + c;
            Bs[r][c] = (gr < K_ && gc < N_) ? B[(size_t)gr * N_ + gc] : 0.f;
        }
        __syncthreads();
        #pragma unroll
        for (int kk = 0; kk < 16; kk++) {
            float a[8], b[8];
            #pragma unroll
            for (int i = 0; i < 8; i++) a[i] = As[kk][row0 + i];
            #pragma unroll
            for (int j = 0; j < 8; j++) b[j] = Bs[kk][col0 + j];
            #pragma unroll
            for (int i = 0; i < 8; i++)
                #pragma unroll
                for (int j = 0; j < 8; j++) acc[i][j] += a[i] * b[j];
        }
        __syncthreads();
    }
    #pragma unroll
    for (int i = 0; i < 8; i++) {
        int gr = bm + row0 + i;
        if (gr < M_) {
            #pragma unroll
            for (int j = 0; j < 8; j++) {
                int gc = bn + col0 + j;
                if (gc < N_) g_bufA[(size_t)gr * N_ + gc] = acc[i][j];
            }
        }
    }
}

// ---------------- aggregation: out[i] = dis_i^2*h[i] + sum_e w_e*h[src_e] (+b, relu / logsoftmax) --
template <int WPN, int CPT, bool LAST>
__global__ void __launch_bounds__(128) k_agg(const float* __restrict__ bias,
                                             float* __restrict__ outp, int d) {
    constexpr int NPB = 4 / WPN;
    int warp = threadIdx.x >> 5, lane = threadIdx.x & 31;
    int node = blockIdx.x * NPB + warp / WPN;
    int wig  = warp % WPN;
    if (node >= NN) return;

    int j[CPT];
    float acc[CPT];
    #pragma unroll
    for (int c = 0; c < CPT; c++) j[c] = lane + wig * 32 + c * (WPN * 32);

    float dn = g_dis[node];
    float selfw = dn * dn;
    const float* hrow = g_bufA + (size_t)node * d;
    #pragma unroll
    for (int c = 0; c < CPT; c++) acc[c] = (j[c] < d) ? selfw * hrow[j[c]] : 0.f;

    int start = g_rowptr[node], end = g_rowptr[node + 1];
    for (int base = start; base < end; base += 32) {
        int e = base + lane;
        int s = 0; float w = 0.f;
        if (e < end) { s = g_src[e]; w = g_w[e]; }
        int cnt = min(32, end - base);
        for (int t = 0; t < cnt; t++) {
            int   ss = __shfl_sync(0xffffffffu, s, t);
            float ww = __shfl_sync(0xffffffffu, w, t);
            const float* hs = g_bufA + (size_t)ss * d;
            #pragma unroll
            for (int c = 0; c < CPT; c++)
                if (j[c] < d) acc[c] += ww * hs[j[c]];
        }
    }

    if (!LAST) {
        #pragma unroll
        for (int c = 0; c < CPT; c++)
            if (j[c] < d)
                g_bufB[(size_t)node * d + j[c]] = fmaxf(acc[c] + bias[j[c]], 0.f);
    } else {
        float v = (j[0] < d) ? acc[0] + bias[j[0]] : -INFINITY;
        float m = v;
        #pragma unroll
        for (int o = 16; o; o >>= 1) m = fmaxf(m, __shfl_xor_sync(0xffffffffu, m, o));
        float ex = (j[0] < d) ? expf(v - m) : 0.f;
        float ssum = ex;
        #pragma unroll
        for (int o = 16; o; o >>= 1) ssum += __shfl_xor_sync(0xffffffffu, ssum, o);
        float lse = logf(ssum);
        if (j[0] < d) outp[(size_t)node * d + j[0]] = v - m - lse;
    }
}

// ---------------- batchnorm ----------------
__global__ void k_zero_stats() {
    int i = threadIdx.x;
    g_sums[i] = 0.f;
    g_sumsq[i] = 0.f;
}

__global__ void k_stats(int d) {
    int col = blockIdx.x * 32 + threadIdx.x;
    int ry = threadIdx.y;
    float s = 0.f, q = 0.f;
    if (col < d) {
        for (int r = blockIdx.y * 8 + ry; r < NN; r += gridDim.y * 8) {
            float x = g_bufB[(size_t)r * d + col];
            s += x; q += x * x;
        }
    }
    __shared__ float sh[8][33], shq[8][33];
    sh[ry][threadIdx.x] = s;
    shq[ry][threadIdx.x] = q;
    __syncthreads();
    if (ry == 0 && col < d) {
        #pragma unroll
        for (int k = 1; k < 8; k++) { s += sh[k][threadIdx.x]; q += shq[k][threadIdx.x]; }
        atomicAdd(&g_sums[col], s);
        atomicAdd(&g_sumsq[col], q);
    }
}

__global__ void k_finalize(const float* __restrict__ gg, const float* __restrict__ bb, int d) {
    int j = threadIdx.x;
    if (j < d) {
        float m   = g_sums[j] * (1.f / NN);
        float var = g_sumsq[j] * (1.f / NN) - m * m;
        float rs  = rsqrtf(var + EPSV);
        float sc  = rs * gg[j];
        g_scale[j] = sc;
        g_shift[j] = bb[j] - m * sc;
    }
}

__global__ void k_bn(int d, int total) {
    int i = blockIdx.x * blockDim.x + threadIdx.x;
    if (i < total) {
        int c = i % d;
        g_bufB[i] = g_bufB[i] * g_scale[c] + g_shift[c];
    }
}

// ---------------- launch ----------------
extern "C" void kernel_launch(void* const* d_in, const int* in_sizes, int n_in,
                              void* d_out, int out_size) {
    const float* x  = (const float*)d_in[0];
    const int*   ei = (const int*)d_in[1];
    static const int DIMS_[7] = {220, 220, 150, 100, 60, 30, 17};
    const float* W[6]; const float* b[6];
    for (int i = 0; i < 6; i++) {
        W[i] = (const float*)d_in[2 + 2 * i];
        b[i] = (const float*)d_in[3 + 2 * i];
    }
    const float* gpar[5]; const float* bpar[5];
    for (int i = 0; i < 5; i++) {
        gpar[i] = (const float*)d_in[14 + 2 * i];
        bpar[i] = (const float*)d_in[15 + 2 * i];
    }

    // preprocessing: degrees, norm coeffs, CSR by dst
    k_init<<<(NN + 255) / 256, 256>>>();
    k_hist<<<(EE + 255) / 256, 256>>>(ei + EE);
    k_dis<<<(NN + 255) / 256, 256>>>();
    int nb = (NN + 511) / 512;
    k_scan1<<<nb, 512>>>();
    k_scan2<<<1, 256>>>(nb);
    k_scan3<<<nb, 512>>>();
    k_fill<<<(EE + 255) / 256, 256>>>(ei);

    for (int L = 0; L < 6; L++) {
        int K_ = DIMS_[L], Nc = DIMS_[L + 1];
        dim3 gg((NN + 127) / 128, (Nc + 127) / 128);
        k_sgemm<<<gg, 256>>>(x, L == 0 ? 1 : 0, W[L], NN, K_, Nc);
        if (L < 5) {
            if (Nc > 128)      k_agg<4, 2, false><<<NN, 128>>>(b[L], nullptr, Nc);
            else if (Nc > 64)  k_agg<4, 1, false><<<NN, 128>>>(b[L], nullptr, Nc);
            else if (Nc > 32)  k_agg<2, 1, false><<<NN / 2, 128>>>(b[L], nullptr, Nc);
            else               k_agg<1, 1, false><<<NN / 4, 128>>>(b[L], nullptr, Nc);
            k_zero_stats<<<1, 256>>>();
            dim3 sg((Nc + 31) / 32, 64);
            k_stats<<<sg, dim3(32, 8)>>>(Nc);
            k_finalize<<<1, 256>>>(gpar[L], bpar[L], Nc);
            int total = NN * Nc;
            k_bn<<<(total + 255) / 256, 256>>>(Nc, total);
        } else {
            k_agg<1, 1, true><<<NN / 4, 128>>>(b[L], (float*)d_out, Nc);
        }
    }
}

// round 3
// speedup vs baseline: 1.5897x; 1.5897x over previous
#include <cuda_runtime.h>
#include <math.h>

#define NN 100000
#define EE 1600000
#define EPSV 1e-5f

// ---------------- device scratch ----------------
__device__ float g_bufA[(size_t)NN * 220];   // GEMM output h (padded strides)
__device__ float g_bufB[(size_t)NN * 220];   // agg output (post-relu, pre-BN), next GEMM input
__device__ int   g_deg[NN];
__device__ float g_dis[NN];
__device__ int   g_cnt[NN];
__device__ int   g_rowptr[NN + 1];
__device__ int   g_cursor[NN];
__device__ int   g_blocksum[256];
__device__ int   g_blockoff[256];
__device__ int   g_src[EE];
__device__ float g_w[EE];
__device__ float g_sums[256];
__device__ float g_sumsq[256];
__device__ float g_scale[256];   // BN scale folded into next GEMM's W rows
__device__ float g_shift[256];   // BN shift
__device__ float g_cvec[256];    // shift @ W : constant row added to GEMM output

// ---------------- preprocessing ----------------
__global__ void k_init() {
    int i = blockIdx.x * blockDim.x + threadIdx.x;
    if (i < NN) g_deg[i] = 1;   // self loop
}

__global__ void k_hist(const int* __restrict__ dst) {
    int e = blockIdx.x * blockDim.x + threadIdx.x;
    if (e < EE) atomicAdd(&g_deg[dst[e]], 1);
}

__global__ void k_dis() {
    int i = blockIdx.x * blockDim.x + threadIdx.x;
    if (i < NN) {
        int dg = g_deg[i];
        g_dis[i] = rsqrtf((float)dg);
        g_cnt[i] = dg - 1;
    }
}

__global__ void k_scan1() {
    __shared__ int sh[512];
    int i = blockIdx.x * 512 + threadIdx.x;
    int v = (i < NN) ? g_cnt[i] : 0;
    sh[threadIdx.x] = v;
    __syncthreads();
    #pragma unroll
    for (int off = 1; off < 512; off <<= 1) {
        int t = (threadIdx.x >= off) ? sh[threadIdx.x - off] : 0;
        __syncthreads();
        sh[threadIdx.x] += t;
        __syncthreads();
    }
    if (i < NN) g_rowptr[i] = sh[threadIdx.x] - v;          // exclusive
    if (threadIdx.x == 511) g_blocksum[blockIdx.x] = sh[511];
}

__global__ void k_scan2(int nb) {
    __shared__ int sh[256];
    int v = (threadIdx.x < nb) ? g_blocksum[threadIdx.x] : 0;
    sh[threadIdx.x] = v;
    __syncthreads();
    #pragma unroll
    for (int off = 1; off < 256; off <<= 1) {
        int t = (threadIdx.x >= off) ? sh[threadIdx.x - off] : 0;
        __syncthreads();
        sh[threadIdx.x] += t;
        __syncthreads();
    }
    if (threadIdx.x < nb) g_blockoff[threadIdx.x] = sh[threadIdx.x] - v;
}

__global__ void k_scan3() {
    int i = blockIdx.x * 512 + threadIdx.x;
    if (i < NN) {
        int r = g_rowptr[i] + g_blockoff[blockIdx.x];
        g_rowptr[i] = r;
        g_cursor[i] = r;
    }
    if (i == 0 && blockIdx.x == 0) g_rowptr[NN] = EE;
}

__global__ void k_fill(const int* __restrict__ ei) {
    int e = blockIdx.x * blockDim.x + threadIdx.x;
    if (e < EE) {
        int s  = ei[e];
        int dv = ei[EE + e];
        float w = g_dis[s] * g_dis[dv];
        int p = atomicAdd(&g_cursor[dv], 1);
        g_src[p] = s;
        g_w[p]   = w;
    }
}

// ---------------- SGEMM: h = A @ (scale∘W) + cvec  -> g_bufA ----------------
// TM=128, TN=32, TK=16, 128 threads, 8x4 micro-tile, double-buffered smem.
// useX==1: A = X (external input). useX==0: A = g_bufB.
__global__ void __launch_bounds__(128) k_sgemm(
    const float* __restrict__ X, int useX, int lda,
    const float* __restrict__ B,   // W [K, N] row-major
    int useScale, int useCvec,
    int M_, int K_, int N_, int ldh)
{
    const float* A = useX ? X : (const float*)g_bufB;
    __shared__ float As[2][16][128];
    __shared__ float Bs[2][16][32];
    int tid = threadIdx.x;
    int bm = blockIdx.x * 128;
    int bn = blockIdx.y * 32;
    int tx = tid & 7, ty = tid >> 3;
    int row0 = ty * 8, col0 = tx * 4;

    float acc[8][4];
    #pragma unroll
    for (int i = 0; i < 8; i++)
        #pragma unroll
        for (int j = 0; j < 4; j++) acc[i][j] = 0.f;

    float4 ra[4];
    float  rb[4];

    auto load_regs = [&](int k0) {
        int gr = bm + tid;
        bool rok = gr < M_;
        const float* arow = A + (size_t)gr * lda + k0;
        if (k0 + 16 <= K_) {
            #pragma unroll
            for (int i = 0; i < 4; i++)
                ra[i] = rok ? *(const float4*)(arow + i * 4) : make_float4(0.f,0.f,0.f,0.f);
        } else {
            #pragma unroll
            for (int i = 0; i < 4; i++) {
                float v[4];
                #pragma unroll
                for (int c = 0; c < 4; c++) {
                    int k = k0 + i * 4 + c;
                    v[c] = (rok && k < K_) ? arow[i * 4 + c] : 0.f;
                }
                ra[i] = make_float4(v[0], v[1], v[2], v[3]);
            }
        }
        #pragma unroll
        for (int i = 0; i < 4; i++) {
            int e = tid + i * 128;
            int kr = e >> 5, kc = e & 31;
            int gk = k0 + kr, gc = bn + kc;
            float v = (gk < K_ && gc < N_) ? B[(size_t)gk * N_ + gc] : 0.f;
            if (useScale && gk < K_) v *= g_scale[gk];
            rb[i] = v;
        }
    };
    auto store_smem = [&](int buf) {
        #pragma unroll
        for (int i = 0; i < 4; i++) {
            As[buf][i*4+0][tid] = ra[i].x;
            As[buf][i*4+1][tid] = ra[i].y;
            As[buf][i*4+2][tid] = ra[i].z;
            As[buf][i*4+3][tid] = ra[i].w;
        }
        #pragma unroll
        for (int i = 0; i < 4; i++) {
            int e = tid + i * 128;
            Bs[buf][e >> 5][e & 31] = rb[i];
        }
    };

    int nsteps = (K_ + 15) >> 4;
    load_regs(0);
    store_smem(0);
    __syncthreads();

    for (int s = 0; s < nsteps; s++) {
        int cur = s & 1;
        if (s + 1 < nsteps) load_regs((s + 1) << 4);
        #pragma unroll
        for (int kk = 0; kk < 16; kk++) {
            float4 a0 = *(const float4*)&As[cur][kk][row0];
            float4 a1 = *(const float4*)&As[cur][kk][row0 + 4];
            float4 b  = *(const float4*)&Bs[cur][kk][col0];
            float av[8] = {a0.x,a0.y,a0.z,a0.w,a1.x,a1.y,a1.z,a1.w};
            float bv[4] = {b.x,b.y,b.z,b.w};
            #pragma unroll
            for (int i = 0; i < 8; i++)
                #pragma unroll
                for (int j = 0; j < 4; j++) acc[i][j] += av[i] * bv[j];
        }
        if (s + 1 < nsteps) store_smem(cur ^ 1);
        __syncthreads();
    }

    float cv[4];
    #pragma unroll
    for (int j = 0; j < 4; j++) {
        int gc = bn + col0 + j;
        cv[j] = (useCvec && gc < N_) ? g_cvec[gc] : 0.f;
    }
    #pragma unroll
    for (int i = 0; i < 8; i++) {
        int gr = bm + row0 + i;
        if (gr < M_) {
            #pragma unroll
            for (int j = 0; j < 4; j++) {
                int gc = bn + col0 + j;
                if (gc < N_) g_bufA[(size_t)gr * ldh + gc] = acc[i][j] + cv[j];
            }
        }
    }
}

// ---------------- aggregation (+bias, relu, fused BN stats / log_softmax) ----
// One warp per node; EPG edges processed concurrently by lane subgroups of G=32/EPG.
template <int EPG, int CPT, bool LAST>
__global__ void __launch_bounds__(256) k_agg(const float* __restrict__ bias,
                                             float* __restrict__ outp,
                                             int d, int s4)
{
    constexpr int G = 32 / EPG;
    int lane = threadIdx.x & 31;
    int warp = threadIdx.x >> 5;
    int sub  = lane & (G - 1);
    int grp  = lane / G;

    __shared__ float sh_sum[256], sh_sq[256];
    if (!LAST) {
        if (threadIdx.x < 256) { sh_sum[threadIdx.x] = 0.f; sh_sq[threadIdx.x] = 0.f; }
        __syncthreads();
    }

    float st_s[CPT * 4], st_q[CPT * 4];
    #pragma unroll
    for (int i = 0; i < CPT * 4; i++) { st_s[i] = 0.f; st_q[i] = 0.f; }

    const float4* __restrict__ H = (const float4*)g_bufA;

    for (int node = blockIdx.x * 8 + warp; node < NN; node += gridDim.x * 8) {
        float4 acc[CPT];
        #pragma unroll
        for (int c = 0; c < CPT; c++) acc[c] = make_float4(0.f,0.f,0.f,0.f);

        float dn = g_dis[node];
        if (grp == 0) {
            float sw = dn * dn;
            #pragma unroll
            for (int c = 0; c < CPT; c++) {
                int j = sub + c * G;
                if (j < s4) {
                    float4 h = H[(size_t)node * s4 + j];
                    acc[c].x = sw * h.x; acc[c].y = sw * h.y;
                    acc[c].z = sw * h.z; acc[c].w = sw * h.w;
                }
            }
        }

        int start = g_rowptr[node], end = g_rowptr[node + 1];
        for (int base = start; base < end; base += 32) {
            int e = base + lane;
            int ssrc = 0; float ww = 0.f;
            if (e < end) { ssrc = g_src[e]; ww = g_w[e]; }
            int cnt = min(32, end - base);
            int steps = (cnt + EPG - 1) / EPG;
            for (int t = 0; t < steps; t++) {
                int ei = t * EPG + grp;                   // < 32 always
                int   s2 = __shfl_sync(0xffffffffu, ssrc, ei);
                float w2 = __shfl_sync(0xffffffffu, ww, ei);  // 0 for padding
                const float4* hr = H + (size_t)s2 * s4;
                #pragma unroll
                for (int c = 0; c < CPT; c++) {
                    int j = sub + c * G;
                    if (j < s4) {
                        float4 h = hr[j];
                        acc[c].x += w2 * h.x; acc[c].y += w2 * h.y;
                        acc[c].z += w2 * h.z; acc[c].w += w2 * h.w;
                    }
                }
            }
        }

        if (EPG > 1) {
            #pragma unroll
            for (int off = G; off < 32; off <<= 1) {
                #pragma unroll
                for (int c = 0; c < CPT; c++) {
                    acc[c].x += __shfl_xor_sync(0xffffffffu, acc[c].x, off);
                    acc[c].y += __shfl_xor_sync(0xffffffffu, acc[c].y, off);
                    acc[c].z += __shfl_xor_sync(0xffffffffu, acc[c].z, off);
                    acc[c].w += __shfl_xor_sync(0xffffffffu, acc[c].w, off);
                }
            }
        }

        if (!LAST) {
            if (grp == 0) {
                #pragma unroll
                for (int c = 0; c < CPT; c++) {
                    int j = sub + c * G;
                    float vals[4] = {acc[c].x, acc[c].y, acc[c].z, acc[c].w};
                    #pragma unroll
                    for (int q = 0; q < 4; q++) {
                        int col = j * 4 + q;
                        if (col < d) {
                            float v = fmaxf(vals[q] + bias[col], 0.f);
                            g_bufB[(size_t)node * (s4 * 4) + col] = v;
                            st_s[c * 4 + q] += v;
                            st_q[c * 4 + q] += v * v;
                        }
                    }
                }
            }
        } else {
            // log_softmax over d columns (CPT==1 here)
            int j = sub;
            float vals[4] = {acc[0].x, acc[0].y, acc[0].z, acc[0].w};
            float lmax = -INFINITY;
            #pragma unroll
            for (int q = 0; q < 4; q++) {
                int col = j * 4 + q;
                float v = (grp == 0 && col < d) ? vals[q] + bias[col] : -INFINITY;
                vals[q] = v;
                lmax = fmaxf(lmax, v);
            }
            #pragma unroll
            for (int off = 1; off < G; off <<= 1)
                lmax = fmaxf(lmax, __shfl_xor_sync(0xffffffffu, lmax, off));
            float lsum = 0.f;
            #pragma unroll
            for (int q = 0; q < 4; q++) {
                int col = j * 4 + q;
                if (grp == 0 && col < d) lsum += expf(vals[q] - lmax);
            }
            #pragma unroll
            for (int off = 1; off < G; off <<= 1)
                lsum += __shfl_xor_sync(0xffffffffu, lsum, off);
            float lse = logf(lsum) + lmax;
            if (grp == 0) {
                #pragma unroll
                for (int q = 0; q < 4; q++) {
                    int col = j * 4 + q;
                    if (col < d) outp[(size_t)node * d + col] = vals[q] - lse;
                }
            }
        }
    }

    if (!LAST) {
        __syncthreads();
        if (grp == 0) {
            #pragma unroll
            for (int c = 0; c < CPT; c++) {
                int j = sub + c * G;
                #pragma unroll
                for (int q = 0; q < 4; q++) {
                    int col = j * 4 + q;
                    if (col < d) {
                        atomicAdd(&sh_sum[col], st_s[c * 4 + q]);
                        atomicAdd(&sh_sq[col],  st_q[c * 4 + q]);
                    }
                }
            }
        }
        __syncthreads();
        if (threadIdx.x < d) {
            atomicAdd(&g_sums[threadIdx.x],  sh_sum[threadIdx.x]);
            atomicAdd(&g_sumsq[threadIdx.x], sh_sq[threadIdx.x]);
        }
    }
}

// ---------------- BN param folding ----------------
__global__ void k_zero_stats() {
    int i = threadIdx.x;
    g_sums[i] = 0.f;
    g_sumsq[i] = 0.f;
}

__global__ void k_finalize(const float* __restrict__ gg, const float* __restrict__ bb, int d) {
    int j = threadIdx.x;
    if (j < d) {
        float m   = g_sums[j] * (1.f / NN);
        float var = g_sumsq[j] * (1.f / NN) - m * m;
        float rs  = rsqrtf(var + EPSV);
        float sc  = rs * gg[j];
        g_scale[j] = sc;
        g_shift[j] = bb[j] - m * sc;
    }
}

__global__ void k_cvec(const float* __restrict__ W, int K_, int N_) {
    int n = threadIdx.x;
    if (n < N_) {
        float s = 0.f;
        for (int k = 0; k < K_; k++) s += g_shift[k] * W[(size_t)k * N_ + n];
        g_cvec[n] = s;
    }
}

// ---------------- launch ----------------
extern "C" void kernel_launch(void* const* d_in, const int* in_sizes, int n_in,
                              void* d_out, int out_size) {
    const float* x  = (const float*)d_in[0];
    const int*   ei = (const int*)d_in[1];
    static const int DIMS_[7] = {220, 220, 150, 100, 60, 30, 17};
    static const int SOUT_[6] = {220, 152, 100, 60, 32, 20};   // padded stride of layer-L output
    const float* W[6]; const float* b[6];
    for (int i = 0; i < 6; i++) {
        W[i] = (const float*)d_in[2 + 2 * i];
        b[i] = (const float*)d_in[3 + 2 * i];
    }
    const float* gpar[5]; const float* bpar[5];
    for (int i = 0; i < 5; i++) {
        gpar[i] = (const float*)d_in[14 + 2 * i];
        bpar[i] = (const float*)d_in[15 + 2 * i];
    }

    // preprocessing: degrees, norm coeffs, CSR by dst
    k_init<<<(NN + 255) / 256, 256>>>();
    k_hist<<<(EE + 255) / 256, 256>>>(ei + EE);
    k_dis<<<(NN + 255) / 256, 256>>>();
    int nb = (NN + 511) / 512;
    k_scan1<<<nb, 512>>>();
    k_scan2<<<1, 256>>>(nb);
    k_scan3<<<nb, 512>>>();
    k_fill<<<(EE + 255) / 256, 256>>>(ei);

    const int AGG_GRID = 1184;

    for (int L = 0; L < 6; L++) {
        int K_ = DIMS_[L], Nc = DIMS_[L + 1];
        int lda = (L == 0) ? 220 : SOUT_[L - 1];
        int ldh = SOUT_[L];

        if (L > 0) {
            k_finalize<<<1, 256>>>(gpar[L - 1], bpar[L - 1], K_);
            k_cvec<<<1, 256>>>(W[L], K_, Nc);
        }

        dim3 gg((NN + 127) / 128, (Nc + 31) / 32);
        k_sgemm<<<gg, 128>>>(x, L == 0 ? 1 : 0, lda, W[L],
                             L > 0 ? 1 : 0, L > 0 ? 1 : 0,
                             NN, K_, Nc, ldh);

        if (L < 5) {
            k_zero_stats<<<1, 256>>>();
            int s4 = ldh / 4;
            if (L <= 1)      k_agg<1, 2, false><<<AGG_GRID, 256>>>(b[L], nullptr, Nc, s4);
            else if (L == 2) k_agg<1, 1, false><<<AGG_GRID, 256>>>(b[L], nullptr, Nc, s4);
            else if (L == 3) k_agg<2, 1, false><<<AGG_GRID, 256>>>(b[L], nullptr, Nc, s4);
            else             k_agg<4, 1, false><<<AGG_GRID, 256>>>(b[L], nullptr, Nc, s4);
        } else {
            k_agg<4, 1, true><<<AGG_GRID, 256>>>(b[L], (float*)d_out, Nc, ldh / 4);
        }
    }
}

// round 5
// speedup vs baseline: 1.8677x; 1.1749x over previous
#include <cuda_runtime.h>
#include <cuda_bf16.h>
#include <math.h>
#include <stdint.h>

#define NN 100000
#define EE 1600000
#define EPSV 1e-5f
#define APAD 72   // bf16 elems per smem row (64 data + 8 pad) -> 144B stride, ldmatrix conflict-free

// ================= device scratch (zero-initialized) =================
__device__ __nv_bfloat16 g_actH[(size_t)NN * 256];   // activation bf16 hi, row stride KP
__device__ __nv_bfloat16 g_actL[(size_t)NN * 256];   // activation bf16 lo
__device__ float g_bufA[(size_t)NN * 224];           // GEMM output fp32, row stride Npad
__device__ __nv_bfloat16 g_hB[57344];                // W^T bf16 hi, [Npad, KP]
__device__ __nv_bfloat16 g_lB[57344];                // W^T bf16 lo
__device__ int   g_deg[NN];
__device__ float g_dis[NN];
__device__ int   g_cnt[NN];
__device__ int   g_rowptr[NN + 1];
__device__ int   g_cursor[NN];
__device__ int   g_blocksum[256];
__device__ int   g_blockoff[256];
__device__ int   g_src[EE];
__device__ float g_w[EE];
__device__ float g_sums[256];
__device__ float g_sumsq[256];
__device__ float g_scale[256];
__device__ float g_shift[256];
__device__ float g_cvec[256];

__device__ __forceinline__ uint32_t smem_u32(const void* p) {
    uint32_t a;
    asm("{ .reg .u64 t; cvta.to.shared.u64 t, %1; cvt.u32.u64 %0, t; }" : "=r"(a) : "l"(p));
    return a;
}

// ================= preprocessing =================
__global__ void k_init() {
    int i = blockIdx.x * blockDim.x + threadIdx.x;
    if (i < NN) g_deg[i] = 1;
}
__global__ void k_hist(const int* __restrict__ dst) {
    int e = blockIdx.x * blockDim.x + threadIdx.x;
    if (e < EE) atomicAdd(&g_deg[dst[e]], 1);
}
__global__ void k_dis() {
    int i = blockIdx.x * blockDim.x + threadIdx.x;
    if (i < NN) {
        int dg = g_deg[i];
        g_dis[i] = rsqrtf((float)dg);
        g_cnt[i] = dg - 1;
    }
}
__global__ void k_scan1() {
    __shared__ int sh[512];
    int i = blockIdx.x * 512 + threadIdx.x;
    int v = (i < NN) ? g_cnt[i] : 0;
    sh[threadIdx.x] = v;
    __syncthreads();
    #pragma unroll
    for (int off = 1; off < 512; off <<= 1) {
        int t = (threadIdx.x >= off) ? sh[threadIdx.x - off] : 0;
        __syncthreads();
        sh[threadIdx.x] += t;
        __syncthreads();
    }
    if (i < NN) g_rowptr[i] = sh[threadIdx.x] - v;
    if (threadIdx.x == 511) g_blocksum[blockIdx.x] = sh[511];
}
__global__ void k_scan2(int nb) {
    __shared__ int sh[256];
    int v = (threadIdx.x < nb) ? g_blocksum[threadIdx.x] : 0;
    sh[threadIdx.x] = v;
    __syncthreads();
    #pragma unroll
    for (int off = 1; off < 256; off <<= 1) {
        int t = (threadIdx.x >= off) ? sh[threadIdx.x - off] : 0;
        __syncthreads();
        sh[threadIdx.x] += t;
        __syncthreads();
    }
    if (threadIdx.x < nb) g_blockoff[threadIdx.x] = sh[threadIdx.x] - v;
}
__global__ void k_scan3() {
    int i = blockIdx.x * 512 + threadIdx.x;
    if (i < NN) {
        int r = g_rowptr[i] + g_blockoff[blockIdx.x];
        g_rowptr[i] = r;
        g_cursor[i] = r;
    }
    if (i == 0 && blockIdx.x == 0) g_rowptr[NN] = EE;
}
__global__ void k_fill(const int* __restrict__ ei) {
    int e = blockIdx.x * blockDim.x + threadIdx.x;
    if (e < EE) {
        int s  = ei[e];
        int dv = ei[EE + e];
        float w = g_dis[s] * g_dis[dv];
        int p = atomicAdd(&g_cursor[dv], 1);
        g_src[p] = s;
        g_w[p]   = w;
    }
}

// ================= conversions / BN folding =================
__global__ void k_convX(const float* __restrict__ x) {
    int i = blockIdx.x;
    int k = threadIdx.x;
    float v = (k < 220) ? x[(size_t)i * 220 + k] : 0.f;
    __nv_bfloat16 hv = __float2bfloat16(v);
    g_actH[(size_t)i * 256 + k] = hv;
    g_actL[(size_t)i * 256 + k] = __float2bfloat16(v - __bfloat162float(hv));
}

__global__ void k_prepW(const float* __restrict__ W, int K_, int N_, int KP, int Npad, int useScale) {
    int idx = blockIdx.x * blockDim.x + threadIdx.x;
    if (idx >= Npad * KP) return;
    int n = idx / KP, k = idx % KP;
    float v = 0.f;
    if (n < N_ && k < K_) {
        v = W[(size_t)k * N_ + n];
        if (useScale) v *= g_scale[k];
    }
    __nv_bfloat16 hv = __float2bfloat16(v);
    g_hB[idx] = hv;
    g_lB[idx] = __float2bfloat16(v - __bfloat162float(hv));
}

__global__ void k_zero_stats() {
    int i = threadIdx.x;
    g_sums[i] = 0.f;
    g_sumsq[i] = 0.f;
}
__global__ void k_finalize(const float* __restrict__ gg, const float* __restrict__ bb, int d) {
    int j = threadIdx.x;
    if (j < d) {
        float m   = g_sums[j] * (1.f / NN);
        float var = g_sumsq[j] * (1.f / NN) - m * m;
        float rs  = rsqrtf(var + EPSV);
        float sc  = rs * gg[j];
        g_scale[j] = sc;
        g_shift[j] = bb[j] - m * sc;
    }
}
__global__ void k_cvec(const float* __restrict__ W, int K_, int N_) {
    int n = threadIdx.x;
    if (n < N_) {
        float s = 0.f;
        for (int k = 0; k < K_; k++) s += g_shift[k] * W[(size_t)k * N_ + n];
        g_cvec[n] = s;
    } else {
        g_cvec[n] = 0.f;
    }
}

// ================= HMMA bf16 3-term split GEMM =================
// D[128 rows, 32 cols per CTA] = (Ah+Al) @ (Bh+Bl)^T, dropping Al*Bl.
// grid: (Npad/32, ceil(NN/128)); blockIdx.x = N chunk (fast) for A reuse in L2.
__device__ __forceinline__ void ldsm4(uint32_t& r0, uint32_t& r1, uint32_t& r2, uint32_t& r3,
                                      uint32_t addr) {
    asm volatile("ldmatrix.sync.aligned.m8n8.x4.shared.b16 {%0,%1,%2,%3}, [%4];"
        : "=r"(r0), "=r"(r1), "=r"(r2), "=r"(r3) : "r"(addr));
}
__device__ __forceinline__ void mma16816(float* d, uint32_t a0, uint32_t a1, uint32_t a2,
                                         uint32_t a3, uint32_t b0, uint32_t b1) {
    asm volatile(
        "mma.sync.aligned.m16n8k16.row.col.f32.bf16.bf16.f32 "
        "{%0,%1,%2,%3}, {%4,%5,%6,%7}, {%8,%9}, {%0,%1,%2,%3};"
        : "+f"(d[0]), "+f"(d[1]), "+f"(d[2]), "+f"(d[3])
        : "r"(a0), "r"(a1), "r"(a2), "r"(a3), "r"(b0), "r"(b1));
}

__global__ void __launch_bounds__(256) k_hgemm(int KP, int Npad, int useCvec) {
    extern __shared__ char smem[];
    __nv_bfloat16* sAh = (__nv_bfloat16*)smem;
    __nv_bfloat16* sAl = sAh + 128 * APAD;
    __nv_bfloat16* sBh = sAl + 128 * APAD;
    __nv_bfloat16* sBl = sBh + 32 * APAD;

    int tid = threadIdx.x;
    int warp = tid >> 5, lane = tid & 31;
    int rowbase = blockIdx.y * 128;
    int colbase = blockIdx.x * 32;

    float acc[4][4];
    #pragma unroll
    for (int j = 0; j < 4; j++)
        #pragma unroll
        for (int q = 0; q < 4; q++) acc[j][q] = 0.f;

    // ldmatrix smem addresses (per-thread, byte offsets added per k-step)
    uint32_t aBaseH = smem_u32(sAh) + (uint32_t)((warp * 16 + (lane & 15)) * APAD * 2) + ((lane >> 4) * 16);
    uint32_t aBaseL = aBaseH + (uint32_t)(128 * APAD * 2);
    int brow = (lane & 7) + ((lane >> 4) << 3);
    uint32_t bColSel = (uint32_t)(((lane >> 3) & 1) * 16);
    uint32_t bBaseH0 = smem_u32(sBh) + (uint32_t)(brow * APAD * 2) + bColSel;
    uint32_t bBaseH1 = bBaseH0 + (uint32_t)(16 * APAD * 2);
    uint32_t bBaseL0 = bBaseH0 + (uint32_t)(32 * APAD * 2);
    uint32_t bBaseL1 = bBaseL0 + (uint32_t)(16 * APAD * 2);

    int nchunks = KP >> 6;
    for (int c = 0; c < nchunks; c++) {
        int k0 = c << 6;
        // A tiles: 128 rows x 64 bf16 hi/lo
        #pragma unroll
        for (int it = 0; it < 4; it++) {
            int u = tid + it * 256;
            int r = u >> 3, q = u & 7;
            int gr = rowbase + r;
            uint4 vh = make_uint4(0u, 0u, 0u, 0u);
            uint4 vl = vh;
            if (gr < NN) {
                size_t off = (size_t)gr * KP + k0 + q * 8;
                vh = *(const uint4*)(g_actH + off);
                vl = *(const uint4*)(g_actL + off);
            }
            *(uint4*)(sAh + r * APAD + q * 8) = vh;
            *(uint4*)(sAl + r * APAD + q * 8) = vl;
        }
        // B tiles: 32 rows x 64 bf16 hi/lo
        {
            int n = tid >> 3, q = tid & 7;
            size_t off = (size_t)(colbase + n) * KP + k0 + q * 8;
            *(uint4*)(sBh + n * APAD + q * 8) = *(const uint4*)(g_hB + off);
            *(uint4*)(sBl + n * APAD + q * 8) = *(const uint4*)(g_lB + off);
        }
        __syncthreads();

        #pragma unroll
        for (int s = 0; s < 4; s++) {
            uint32_t so = (uint32_t)(s * 32);
            uint32_t ah0, ah1, ah2, ah3, al0, al1, al2, al3;
            ldsm4(ah0, ah1, ah2, ah3, aBaseH + so);
            ldsm4(al0, al1, al2, al3, aBaseL + so);
            uint32_t bh[8], bl[8];
            ldsm4(bh[0], bh[1], bh[2], bh[3], bBaseH0 + so);
            ldsm4(bh[4], bh[5], bh[6], bh[7], bBaseH1 + so);
            ldsm4(bl[0], bl[1], bl[2], bl[3], bBaseL0 + so);
            ldsm4(bl[4], bl[5], bl[6], bl[7], bBaseL1 + so);
            #pragma unroll
            for (int j = 0; j < 4; j++) {
                mma16816(acc[j], ah0, ah1, ah2, ah3, bh[j * 2], bh[j * 2 + 1]);
                mma16816(acc[j], ah0, ah1, ah2, ah3, bl[j * 2], bl[j * 2 + 1]);
                mma16816(acc[j], al0, al1, al2, al3, bh[j * 2], bh[j * 2 + 1]);
            }
        }
        __syncthreads();
    }

    // epilogue: store fp32 + cvec
    int r0 = rowbase + warp * 16 + (lane >> 2);
    int c0 = colbase + (lane & 3) * 2;
    #pragma unroll
    for (int j = 0; j < 4; j++) {
        int col = c0 + j * 8;
        float cv0 = useCvec ? g_cvec[col] : 0.f;
        float cv1 = useCvec ? g_cvec[col + 1] : 0.f;
        if (r0 < NN) {
            float* p = g_bufA + (size_t)r0 * Npad + col;
            p[0] = acc[j][0] + cv0;
            p[1] = acc[j][1] + cv1;
        }
        if (r0 + 8 < NN) {
            float* p = g_bufA + (size_t)(r0 + 8) * Npad + col;
            p[0] = acc[j][2] + cv0;
            p[1] = acc[j][3] + cv1;
        }
    }
}

// ================= aggregation (+bias, relu, bf16 split-out, fused BN stats / log_softmax) ===
template <int EPG, int CPT, bool LAST>
__global__ void __launch_bounds__(256) k_agg(const float* __restrict__ bias,
                                             float* __restrict__ outp,
                                             int d, int s4, int KPn)
{
    constexpr int G = 32 / EPG;
    int lane = threadIdx.x & 31;
    int warp = threadIdx.x >> 5;
    int sub  = lane & (G - 1);
    int grp  = lane / G;

    __shared__ float sh_sum[256], sh_sq[256];
    if (!LAST) {
        if (threadIdx.x < 256) { sh_sum[threadIdx.x] = 0.f; sh_sq[threadIdx.x] = 0.f; }
        __syncthreads();
    }

    float st_s[CPT * 4], st_q[CPT * 4];
    #pragma unroll
    for (int i = 0; i < CPT * 4; i++) { st_s[i] = 0.f; st_q[i] = 0.f; }

    const float4* __restrict__ H = (const float4*)g_bufA;
    const __nv_bfloat16 bz = __float2bfloat16(0.f);

    for (int node = blockIdx.x * 8 + warp; node < NN; node += gridDim.x * 8) {
        float4 acc[CPT];
        #pragma unroll
        for (int c = 0; c < CPT; c++) acc[c] = make_float4(0.f, 0.f, 0.f, 0.f);

        float dn = g_dis[node];
        if (grp == 0) {
            float sw = dn * dn;
            #pragma unroll
            for (int c = 0; c < CPT; c++) {
                int j = sub + c * G;
                if (j < s4) {
                    float4 h = H[(size_t)node * s4 + j];
                    acc[c].x = sw * h.x; acc[c].y = sw * h.y;
                    acc[c].z = sw * h.z; acc[c].w = sw * h.w;
                }
            }
        }

        int start = g_rowptr[node], end = g_rowptr[node + 1];
        for (int base = start; base < end; base += 32) {
            int e = base + lane;
            int ssrc = 0; float ww = 0.f;
            if (e < end) { ssrc = g_src[e]; ww = g_w[e]; }
            int cnt = min(32, end - base);
            int steps = (cnt + EPG - 1) / EPG;
            for (int t = 0; t < steps; t++) {
                int ei = t * EPG + grp;
                int   s2 = __shfl_sync(0xffffffffu, ssrc, ei);
                float w2 = __shfl_sync(0xffffffffu, ww, ei);
                const float4* hr = H + (size_t)s2 * s4;
                #pragma unroll
                for (int c = 0; c < CPT; c++) {
                    int j = sub + c * G;
                    if (j < s4) {
                        float4 h = hr[j];
                        acc[c].x += w2 * h.x; acc[c].y += w2 * h.y;
                        acc[c].z += w2 * h.z; acc[c].w += w2 * h.w;
                    }
                }
            }
        }

        if (EPG > 1) {
            #pragma unroll
            for (int off = G; off < 32; off <<= 1) {
                #pragma unroll
                for (int c = 0; c < CPT; c++) {
                    acc[c].x += __shfl_xor_sync(0xffffffffu, acc[c].x, off);
                    acc[c].y += __shfl_xor_sync(0xffffffffu, acc[c].y, off);
                    acc[c].z += __shfl_xor_sync(0xffffffffu, acc[c].z, off);
                    acc[c].w += __shfl_xor_sync(0xffffffffu, acc[c].w, off);
                }
            }
        }

        if (!LAST) {
            if (grp == 0) {
                #pragma unroll
                for (int c = 0; c < CPT; c++) {
                    int j = sub + c * G;
                    float vals[4] = {acc[c].x, acc[c].y, acc[c].z, acc[c].w};
                    #pragma unroll
                    for (int q = 0; q < 4; q++) {
                        int col = j * 4 + q;
                        if (col < d) {
                            float v = fmaxf(vals[q] + bias[col], 0.f);
                            __nv_bfloat16 hv = __float2bfloat16(v);
                            g_actH[(size_t)node * KPn + col] = hv;
                            g_actL[(size_t)node * KPn + col] =
                                __float2bfloat16(v - __bfloat162float(hv));
                            st_s[c * 4 + q] += v;
                            st_q[c * 4 + q] += v * v;
                        }
                    }
                }
                for (int col = d + sub; col < KPn; col += G) {
                    g_actH[(size_t)node * KPn + col] = bz;
                    g_actL[(size_t)node * KPn + col] = bz;
                }
            }
        } else {
            int j = sub;
            float vals[4] = {acc[0].x, acc[0].y, acc[0].z, acc[0].w};
            float lmax = -INFINITY;
            #pragma unroll
            for (int q = 0; q < 4; q++) {
                int col = j * 4 + q;
                float v = (grp == 0 && col < d) ? vals[q] + bias[col] : -INFINITY;
                vals[q] = v;
                lmax = fmaxf(lmax, v);
            }
            #pragma unroll
            for (int off = 1; off < G; off <<= 1)
                lmax = fmaxf(lmax, __shfl_xor_sync(0xffffffffu, lmax, off));
            float lsum = 0.f;
            #pragma unroll
            for (int q = 0; q < 4; q++) {
                int col = j * 4 + q;
                if (grp == 0 && col < d) lsum += expf(vals[q] - lmax);
            }
            #pragma unroll
            for (int off = 1; off < G; off <<= 1)
                lsum += __shfl_xor_sync(0xffffffffu, lsum, off);
            float lse = logf(lsum) + lmax;
            if (grp == 0) {
                #pragma unroll
                for (int q = 0; q < 4; q++) {
                    int col = j * 4 + q;
                    if (col < d) outp[(size_t)node * d + col] = vals[q] - lse;
                }
            }
        }
    }

    if (!LAST) {
        __syncthreads();
        if (grp == 0) {
            #pragma unroll
            for (int c = 0; c < CPT; c++) {
                int j = sub + c * G;
                #pragma unroll
                for (int q = 0; q < 4; q++) {
                    int col = j * 4 + q;
                    if (col < d) {
                        atomicAdd(&sh_sum[col], st_s[c * 4 + q]);
                        atomicAdd(&sh_sq[col],  st_q[c * 4 + q]);
                    }
                }
            }
        }
        __syncthreads();
        if (threadIdx.x < d) {
            atomicAdd(&g_sums[threadIdx.x],  sh_sum[threadIdx.x]);
            atomicAdd(&g_sumsq[threadIdx.x], sh_sq[threadIdx.x]);
        }
    }
}

// ================= launch =================
extern "C" void kernel_launch(void* const* d_in, const int* in_sizes, int n_in,
                              void* d_out, int out_size) {
    const float* x  = (const float*)d_in[0];
    const int*   ei = (const int*)d_in[1];
    static const int DIMS_[7] = {220, 220, 150, 100, 60, 30, 17};
    static const int KPt[6]   = {256, 256, 192, 128, 64, 64};   // K stride (bf16 buffers)
    static const int NPADt[6] = {224, 160, 128, 64, 32, 32};    // output cols padded
    const float* W[6]; const float* b[6];
    for (int i = 0; i < 6; i++) {
        W[i] = (const float*)d_in[2 + 2 * i];
        b[i] = (const float*)d_in[3 + 2 * i];
    }
    const float* gpar[5]; const float* bpar[5];
    for (int i = 0; i < 5; i++) {
        gpar[i] = (const float*)d_in[14 + 2 * i];
        bpar[i] = (const float*)d_in[15 + 2 * i];
    }

    // preprocessing
    k_init<<<(NN + 255) / 256, 256>>>();
    k_hist<<<(EE + 255) / 256, 256>>>(ei + EE);
    k_dis<<<(NN + 255) / 256, 256>>>();
    int nb = (NN + 511) / 512;
    k_scan1<<<nb, 512>>>();
    k_scan2<<<1, 256>>>(nb);
    k_scan3<<<nb, 512>>>();
    k_fill<<<(EE + 255) / 256, 256>>>(ei);
    k_convX<<<NN, 256>>>(x);

    const int AGG_GRID = 1184;
    const int ROW_BLKS = (NN + 127) / 128;   // 782
    const size_t SMEM_GEMM = (size_t)(128 * APAD + 128 * APAD + 32 * APAD + 32 * APAD) * 2;

    for (int L = 0; L < 6; L++) {
        int K_ = DIMS_[L], Nc = DIMS_[L + 1];
        int KP = KPt[L], Npad = NPADt[L];

        if (L > 0) {
            k_finalize<<<1, 256>>>(gpar[L - 1], bpar[L - 1], K_);
            k_cvec<<<1, 256>>>(W[L], K_, Nc);
        }
        k_prepW<<<(Npad * KP + 255) / 256, 256>>>(W[L], K_, Nc, KP, Npad, L > 0 ? 1 : 0);

        dim3 gg(Npad / 32, ROW_BLKS);
        k_hgemm<<<gg, 256, SMEM_GEMM>>>(KP, Npad, L > 0 ? 1 : 0);

        if (L < 5) {
            k_zero_stats<<<1, 256>>>();
            int s4 = Npad / 4;
            int KPn = KPt[L + 1];
            if (L <= 1)      k_agg<1, 2, false><<<AGG_GRID, 256>>>(b[L], nullptr, Nc, s4, KPn);
            else if (L == 2) k_agg<1, 1, false><<<AGG_GRID, 256>>>(b[L], nullptr, Nc, s4, KPn);
            else if (L == 3) k_agg<2, 1, false><<<AGG_GRID, 256>>>(b[L], nullptr, Nc, s4, KPn);
            else             k_agg<4, 1, false><<<AGG_GRID, 256>>>(b[L], nullptr, Nc, s4, KPn);
        } else {
            k_agg<4, 1, true><<<AGG_GRID, 256>>>(b[L], (float*)d_out, Nc, Npad / 4, 0);
        }
    }
}